// round 8
// baseline (speedup 1.0000x reference)
#include <cuda_runtime.h>
#include <cstdint>

// ---------------------------------------------------------------------------
// QuantumLayer. Two kernels:
//  k_noise: grid 2048 x 128thr, 8 elems/thread as adjacent pairs -> float2
//           stores; 4 independent threefry chains per iteration. Writes m2
//           and per-block partial sums.
//  k_scale: grid 512 x 256thr, 4 float4/thread PREFETCHED before the rinv
//           barrier so data-load latency overlaps the partials load.
// ---------------------------------------------------------------------------

__device__ float g_partials[2048];

// ----------------------------- complex helpers -----------------------------
__device__ __forceinline__ float2 cmul(float2 a, float2 b) {
    return make_float2(a.x * b.x - a.y * b.y, a.x * b.y + a.y * b.x);
}
__device__ __forceinline__ float2 cadd(float2 a, float2 b) {
    return make_float2(a.x + b.x, a.y + b.y);
}

struct C2x2 { float2 m00, m01, m10, m11; };

__device__ __forceinline__ C2x2 mmul(const C2x2& A, const C2x2& B) {  // A*B
    C2x2 R;
    R.m00 = cadd(cmul(A.m00, B.m00), cmul(A.m01, B.m10));
    R.m01 = cadd(cmul(A.m00, B.m01), cmul(A.m01, B.m11));
    R.m10 = cadd(cmul(A.m10, B.m00), cmul(A.m11, B.m10));
    R.m11 = cadd(cmul(A.m10, B.m01), cmul(A.m11, B.m11));
    return R;
}

__device__ __forceinline__ float2 shf2(float2 v, int off) {
    return make_float2(__shfl_down_sync(0xFFFFFFFFu, v.x, off),
                       __shfl_down_sync(0xFFFFFFFFu, v.y, off));
}
__device__ __forceinline__ C2x2 shfm(const C2x2& P, int off) {
    C2x2 Q;
    Q.m00 = shf2(P.m00, off); Q.m01 = shf2(P.m01, off);
    Q.m10 = shf2(P.m10, off); Q.m11 = shf2(P.m11, off);
    return Q;
}

// ----------------------------- threefry-2x32 -------------------------------
// two counters (ja, jb), same key: rounds interleaved across both chains.
__device__ __forceinline__ uint2 threefry_pair(uint32_t k0, uint32_t k1,
                                               uint32_t ja, uint32_t jb) {
    uint32_t ks2 = 0x1BD11BDAu ^ k0 ^ k1;
    uint32_t a0 = k0, a1 = ja + k1;
    uint32_t b0 = k0, b1 = jb + k1;
#define TF2(r) { a0 += a1; b0 += b1; \
                 a1 = __funnelshift_l(a1, a1, (r)); b1 = __funnelshift_l(b1, b1, (r)); \
                 a1 ^= a0; b1 ^= b0; }
    TF2(13) TF2(15) TF2(26) TF2(6)
    a0 += k1;  b0 += k1;  a1 += ks2 + 1u; b1 += ks2 + 1u;
    TF2(17) TF2(29) TF2(16) TF2(24)
    a0 += ks2; b0 += ks2; a1 += k0 + 2u;  b1 += k0 + 2u;
    TF2(13) TF2(15) TF2(26) TF2(6)
    a0 += k0;  b0 += k0;  a1 += k1 + 3u;  b1 += k1 + 3u;
    TF2(17) TF2(29) TF2(16) TF2(24)
    a0 += k1;  b0 += k1;  a1 += ks2 + 4u; b1 += ks2 + 4u;
    TF2(13) TF2(15) TF2(26) TF2(6)
    a0 += ks2; b0 += ks2; a1 += k0 + 5u;  b1 += k0 + 5u;
#undef TF2
    return make_uint2(a0 ^ a1, b0 ^ b1);   // lane0 ^ lane1 per counter
}

// ------------------- XLA erf_inv (f32), fast log variant -------------------
__device__ __forceinline__ float xla_erfinv_fast(float x) {
    float w = -__logf(fmaf(x, -x, 1.0f));
    float p;
    if (w < 5.0f) {
        w -= 2.5f;
        p = 2.81022636e-08f;
        p = fmaf(p, w, 3.43273939e-07f);
        p = fmaf(p, w, -3.5233877e-06f);
        p = fmaf(p, w, -4.39150654e-06f);
        p = fmaf(p, w, 0.00021858087f);
        p = fmaf(p, w, -0.00125372503f);
        p = fmaf(p, w, -0.00417768164f);
        p = fmaf(p, w, 0.246640727f);
        p = fmaf(p, w, 1.50140941f);
    } else {
        w = sqrtf(w) - 3.0f;
        p = -0.000200214257f;
        p = fmaf(p, w, 0.000100950558f);
        p = fmaf(p, w, 0.00134934322f);
        p = fmaf(p, w, -0.00367342844f);
        p = fmaf(p, w, 0.00573950773f);
        p = fmaf(p, w, -0.0076224613f);
        p = fmaf(p, w, 0.00943887047f);
        p = fmaf(p, w, 1.00167406f);
        p = fmaf(p, w, 2.83297682f);
    }
    return p * x;
}

__device__ __forceinline__ float bits_to_noise(uint32_t bits) {
    const float LO = -0.99999994039535522461f;   // nextafter(-1, 0)
    float f = __uint_as_float((bits >> 9) | 0x3f800000u) - 1.0f;  // [0,1) exact
    float u = fmaxf(LO, fmaf(f, 2.0f, LO));
    return xla_erfinv_fast(u) * 0.01f;
}

// ---------------------------------------------------------------------------
// K1: noise + m2.  grid = 2048 (256 rows x 8 segs), block = 128.
// Thread t handles adjacent pairs (2t, 2t+1) at 4 strided offsets -> float2
// stores; amp fixup lives entirely in thread 0 of seg 0.
// ---------------------------------------------------------------------------
__global__ void k_noise(
    const float* __restrict__ rx, const float* __restrict__ ry,
    const float* __restrict__ rz, float* __restrict__ out,
    uint32_t kre0, uint32_t kre1, uint32_t kim0, uint32_t kim1) {

    const int t   = threadIdx.x;
    const int bid = blockIdx.x;
    const int row = bid >> 3;
    const int seg = bid & 7;

    // ---- warp 0 of seg==0 blocks: ordered product of 78 gate matrices ----
    float2 amp0 = {0.f, 0.f}, amp1 = {0.f, 0.f};
    if (seg == 0 && t < 32) {
        const int lane = t;
        const int lo = (lane * 78) >> 5;
        const int hi = ((lane + 1) * 78) >> 5;
        C2x2 P;
        P.m00 = {1.f, 0.f}; P.m01 = {0.f, 0.f};
        P.m10 = {0.f, 0.f}; P.m11 = {1.f, 0.f};
        for (int g = lo; g < hi; ++g) {
            float a; int axis;
            if (g < 26)      { a = __ldg(rx + g);      axis = 0; }
            else if (g < 52) { a = __ldg(ry + g - 26); axis = 1; }
            else             { a = __ldg(rz + g - 52); axis = 2; }
            float s, c;
            sincosf(0.5f * a, &s, &c);
            float2 e00, e01, e10, e11;
            if (axis == 0) {        // rx
                e00 = {c, 0.f}; e01 = {0.f, -s}; e10 = {0.f, -s}; e11 = {c, 0.f};
            } else if (axis == 1) { // ry
                e00 = {c, 0.f}; e01 = {-s, 0.f}; e10 = {s, 0.f};  e11 = {c, 0.f};
            } else {                // rz
                e00 = {c, -s};  e01 = {0.f, 0.f}; e10 = {0.f, 0.f}; e11 = {c, s};
            }
            // fold the reference's in-place aliasing bug
            C2x2 E;
            E.m00 = e00;
            E.m01 = e01;
            E.m10 = cmul(e10, e00);
            E.m11 = cadd(cmul(e10, e01), e11);
            P = mmul(E, P);
        }
        #pragma unroll
        for (int off = 1; off < 32; off <<= 1) {
            C2x2 Q = shfm(P, off);
            if ((lane & (2 * off - 1)) == 0) P = mmul(Q, P);
        }
        amp0.x = __shfl_sync(0xFFFFFFFFu, P.m00.x, 0);
        amp0.y = __shfl_sync(0xFFFFFFFFu, P.m00.y, 0);
        amp1.x = __shfl_sync(0xFFFFFFFFu, P.m10.x, 0);
        amp1.y = __shfl_sync(0xFFFFFFFFu, P.m10.y, 0);
    }

    // element pair base: adjacent elements 2t, 2t+1 within the segment
    const uint32_t base = (uint32_t)(row * 8192 + seg * 1024 + t * 2);
    float2* o2 = reinterpret_cast<float2*>(out);
    float local = 0.0f;

    // k = 0 peeled: amp add lives only here (thread 0 of seg 0 owns d=0,1)
    {
        const uint32_t ja = base, jb = base + 1;
        uint2 br = threefry_pair(kre0, kre1, ja, jb);
        uint2 bi = threefry_pair(kim0, kim1, ja, jb);
        float rea = bits_to_noise(br.x), reb = bits_to_noise(br.y);
        float ima = bits_to_noise(bi.x), imb = bits_to_noise(bi.y);
        if (seg == 0 && t == 0) {
            rea += amp0.x; ima += amp0.y;
            reb += amp1.x; imb += amp1.y;
        }
        float m2a = fmaf(rea, rea, ima * ima);
        float m2b = fmaf(reb, reb, imb * imb);
        local += m2a + m2b;
        o2[ja >> 1] = make_float2(m2a, m2b);
    }
#pragma unroll
    for (int k = 1; k < 4; k++) {
        const uint32_t ja = base + k * 256, jb = ja + 1;
        uint2 br = threefry_pair(kre0, kre1, ja, jb);
        uint2 bi = threefry_pair(kim0, kim1, ja, jb);
        float rea = bits_to_noise(br.x), reb = bits_to_noise(br.y);
        float ima = bits_to_noise(bi.x), imb = bits_to_noise(bi.y);
        float m2a = fmaf(rea, rea, ima * ima);
        float m2b = fmaf(reb, reb, imb * imb);
        local += m2a + m2b;
        o2[ja >> 1] = make_float2(m2a, m2b);
    }

    // ---- block reduction (4 warps) ----
    __shared__ float wsum[4];
#pragma unroll
    for (int o = 16; o; o >>= 1) local += __shfl_xor_sync(0xFFFFFFFFu, local, o);
    if ((t & 31) == 0) wsum[t >> 5] = local;
    __syncthreads();
    if (t == 0) {
        g_partials[bid] = wsum[0] + wsum[1] + wsum[2] + wsum[3];
    }
}

// ---------------------------------------------------------------------------
// K2: grid = 512 (256 rows x 2 halves), block = 256, 4 float4/thread.
// Data loads are issued BEFORE the rinv computation/barrier so their latency
// overlaps the partials load.
// ---------------------------------------------------------------------------
__global__ __launch_bounds__(256) void k_scale(float* __restrict__ out) {
    const int bid = blockIdx.x;
    const int t   = threadIdx.x;
    const int row = bid >> 1;

    float4* o4 = reinterpret_cast<float4*>(out);
    const int fbase = (bid << 10) + t;          // bid*1024 + t
    // prefetch: 4 loads in flight before anything else
    float4 v0 = o4[fbase];
    float4 v1 = o4[fbase + 256];
    float4 v2 = o4[fbase + 512];
    float4 v3 = o4[fbase + 768];

    __shared__ float rinv_s;
    if (t < 32) {
        float v = (t < 8) ? __ldcg(&g_partials[row * 8 + t]) : 0.0f;
        v += __shfl_xor_sync(0xFFFFFFFFu, v, 4);
        v += __shfl_xor_sync(0xFFFFFFFFu, v, 2);
        v += __shfl_xor_sync(0xFFFFFFFFu, v, 1);
        if (t == 0) rinv_s = rsqrtf(v);
    }
    __syncthreads();
    const float rinv = rinv_s;

    v0.x = sqrtf(v0.x) * rinv; v0.y = sqrtf(v0.y) * rinv;
    v0.z = sqrtf(v0.z) * rinv; v0.w = sqrtf(v0.w) * rinv;
    v1.x = sqrtf(v1.x) * rinv; v1.y = sqrtf(v1.y) * rinv;
    v1.z = sqrtf(v1.z) * rinv; v1.w = sqrtf(v1.w) * rinv;
    v2.x = sqrtf(v2.x) * rinv; v2.y = sqrtf(v2.y) * rinv;
    v2.z = sqrtf(v2.z) * rinv; v2.w = sqrtf(v2.w) * rinv;
    v3.x = sqrtf(v3.x) * rinv; v3.y = sqrtf(v3.y) * rinv;
    v3.z = sqrtf(v3.z) * rinv; v3.w = sqrtf(v3.w) * rinv;

    o4[fbase]       = v0;
    o4[fbase + 256] = v1;
    o4[fbase + 512] = v2;
    o4[fbase + 768] = v3;
}

// ------------------------- host-side threefry ------------------------------
static inline uint32_t h_rotl(uint32_t x, int r) { return (x << r) | (x >> (32 - r)); }
static void h_threefry(uint32_t k0, uint32_t k1, uint32_t x0, uint32_t x1,
                       uint32_t* o0, uint32_t* o1) {
    uint32_t ks2 = 0x1BD11BDAu ^ k0 ^ k1;
#define HTF(r) { x0 += x1; x1 = h_rotl(x1, (r)); x1 ^= x0; }
    x0 += k0;  x1 += k1;
    HTF(13) HTF(15) HTF(26) HTF(6)
    x0 += k1;  x1 += ks2 + 1u;
    HTF(17) HTF(29) HTF(16) HTF(24)
    x0 += ks2; x1 += k0 + 2u;
    HTF(13) HTF(15) HTF(26) HTF(6)
    x0 += k0;  x1 += k1 + 3u;
    HTF(17) HTF(29) HTF(16) HTF(24)
    x0 += k1;  x1 += ks2 + 4u;
    HTF(13) HTF(15) HTF(26) HTF(6)
    x0 += ks2; x1 += k0 + 5u;
#undef HTF
    *o0 = x0; *o1 = x1;
}

// ---------------------------------------------------------------------------
extern "C" void kernel_launch(void* const* d_in, const int* in_sizes, int n_in,
                              void* d_out, int out_size) {
    // metadata order: x (unused), rx_params, ry_params, rz_params
    const float* rx = (const float*)d_in[1];
    const float* ry = (const float*)d_in[2];
    const float* rz = (const float*)d_in[3];
    float* out = (float*)d_out;

    uint32_t kre0, kre1, kim0, kim1;
    h_threefry(0u, 42u, 0u, 0u, &kre0, &kre1);
    h_threefry(0u, 42u, 0u, 1u, &kim0, &kim1);

    k_noise<<<2048, 128>>>(rx, ry, rz, out, kre0, kre1, kim0, kim1);
    k_scale<<<512, 256>>>(out);
}